// round 5
// baseline (speedup 1.0000x reference)
#include <cuda_runtime.h>
#include <cstdint>

#define BB 512
#define TT 2000
#define HH 50
#define CH 32
#define HSTRIDE 68     // floats per hist row, 16B-aligned rows

typedef unsigned long long ull;

__device__ __forceinline__ ull packf2(float a, float b) {
    ull r;
    asm("mov.b64 %0, {%1, %2};" : "=l"(r) : "f"(a), "f"(b));
    return r;
}
__device__ __forceinline__ void unpackf2(ull v, float& lo, float& hi) {
    asm("mov.b64 {%0, %1}, %2;" : "=f"(lo), "=f"(hi) : "l"(v));
}
#define FMA2(acc, a, b) \
    asm("fma.rn.f32x2 %0, %1, %2, %0;" : "+l"(acc) : "l"(a), "l"(b))
#define ADD2(dst, a, b) \
    asm("add.rn.f32x2 %0, %1, %2;" : "=l"(dst) : "l"(a), "l"(b))

__global__ __launch_bounds__(128, 1)
void rnn_kernel(const float* __restrict__ x,
                const float* __restrict__ W_ih,
                const float* __restrict__ W_hh,
                const float* __restrict__ b_ih,
                const float* __restrict__ b_hh,
                const float* __restrict__ W_out,
                const float* __restrict__ b_out,
                float* __restrict__ y)
{
    // per-warp 33-row history: step s reads row s, writes row s+1; no syncs.
    __shared__ __align__(16) float hist[4][CH + 1][HSTRIDE];   // 35,904 B
    __shared__ __align__(16) float xs[4][2][CH][4];            //  4,096 B
    __shared__ ull  wosh[3][25];
    __shared__ float bosh[3];

    const int tid  = threadIdx.x;
    const int warp = tid >> 5;
    const int lane = tid & 31;
    const int b = blockIdx.x * 4 + warp;

    if (tid < 75) {
        const int d = tid / 25, q = tid % 25;
        wosh[d][q] = packf2(W_out[d * HH + 2 * q], W_out[d * HH + 2 * q + 1]);
    }
    if (tid < 3) bosh[tid] = b_out[tid];

    const int j0 = lane;            // < 50 always
    const int j1 = lane + 32;       // valid for lanes 0..17
    const bool j1v = (j1 < HH);

    // per-lane packed W_hh rows (25 k-pairs each)
    ull w0[25], w1[25];
#pragma unroll
    for (int q = 0; q < 25; q++) {
        w0[q] = packf2(W_hh[j0 * HH + 2 * q], W_hh[j0 * HH + 2 * q + 1]);
        w1[q] = j1v ? packf2(W_hh[j1 * HH + 2 * q], W_hh[j1 * HH + 2 * q + 1]) : 0ull;
    }
    const float wi0a = W_ih[j0 * 3 + 0], wi0b = W_ih[j0 * 3 + 1], wi0c = W_ih[j0 * 3 + 2];
    const float bias0 = b_ih[j0] + b_hh[j0];
    const float wi1a = j1v ? W_ih[j1 * 3 + 0] : 0.f;
    const float wi1b = j1v ? W_ih[j1 * 3 + 1] : 0.f;
    const float wi1c = j1v ? W_ih[j1 * 3 + 2] : 0.f;
    const float bias1 = j1v ? (b_ih[j1] + b_hh[j1]) : 0.f;

    float* const hwarp = &hist[warp][0][0];
    // h_{-1} = 0 in row 0 (cols 0..63; 50..63 stay 0 forever — step stores write them as 0)
    hwarp[lane] = 0.f;
    hwarp[lane + 32] = 0.f;

    const float* __restrict__ xb = x + (size_t)b * TT * 3;
    float* __restrict__ yb = y + (size_t)b * TT * 3;

    // stage x chunk 0 (96 floats, lanes 0..23 one float4 each)
    if (lane < 24) {
        const float4 v = *reinterpret_cast<const float4*>(xb + lane * 4);
        const float c[4] = {v.x, v.y, v.z, v.w};
#pragma unroll
        for (int i = 0; i < 4; i++) {
            const int gi = lane * 4 + i;
            xs[warp][0][gi / 3][gi % 3] = c[i];
        }
    }
    __syncthreads();   // wosh/bosh visibility only (outside hot loop)

    int xbuf = 0;
    for (int base = 0; base < TT; base += CH) {
        const int cnt = min(CH, TT - base);   // 32 or 16, both %4==0

        // register prefetch of next chunk's x (consumed after the step loop)
        float4 pf;
        const int ncnt = min(CH, TT - base - CH);
        const bool dopf = (base + CH < TT) && (lane * 4 < 3 * ncnt);
        if (dopf) pf = *reinterpret_cast<const float4*>(xb + 3 * (base + CH) + lane * 4);

        // ---- recurrence: no syncs, warp-private smem, constant offsets ----
        for (int g = 0; g < cnt; g += 4) {
#pragma unroll
            for (int u = 0; u < 4; u++) {
                const int s = g + u;
                const float4 xv = *reinterpret_cast<const float4*>(&xs[warp][xbuf][s][0]);
                const float xh0 = fmaf(xv.z, wi0c, fmaf(xv.y, wi0b, fmaf(xv.x, wi0a, bias0)));
                const float xh1 = fmaf(xv.z, wi1c, fmaf(xv.y, wi1b, fmaf(xv.x, wi1a, bias1)));

                const float* hr = hwarp + s * HSTRIDE;
                // xh folded into accumulator init -> 3-level tail
                ull a0 = packf2(xh0, 0.f), a1 = 0ull;
                ull b0 = packf2(xh1, 0.f), b1 = 0ull;
#pragma unroll
                for (int p = 0; p < 12; p++) {
                    const ulonglong2 hv = *reinterpret_cast<const ulonglong2*>(hr + 4 * p);
                    FMA2(a0, hv.x, w0[2 * p]);
                    FMA2(b0, hv.x, w1[2 * p]);
                    FMA2(a1, hv.y, w0[2 * p + 1]);
                    FMA2(b1, hv.y, w1[2 * p + 1]);
                }
                const ull hl = *reinterpret_cast<const ull*>(hr + 48);  // h[48..49]
                FMA2(a0, hl, w0[24]);
                FMA2(b0, hl, w1[24]);

                ull s0, s1;
                ADD2(s0, a0, a1);
                ADD2(s1, b0, b1);
                float l0, u0, l1, u1;
                unpackf2(s0, l0, u0);
                unpackf2(s1, l1, u1);
                const float h0 = fmaxf(l0 + u0, 0.f);
                const float h1 = fmaxf(l1 + u1, 0.f);   // exactly 0 for padded j1

                float* hw = hwarp + (s + 1) * HSTRIDE;
                hw[lane] = h0;
                hw[lane + 32] = h1;    // keeps cols 50..63 at 0
            }
        }

        // carry h into row 0 for next chunk (same warp, in-order smem)
        hwarp[lane] = hwarp[cnt * HSTRIDE + lane];
        hwarp[lane + 32] = hwarp[cnt * HSTRIDE + lane + 32];

        // stage prefetched x
        if (dopf) {
            const float c[4] = {pf.x, pf.y, pf.z, pf.w};
#pragma unroll
            for (int i = 0; i < 4; i++) {
                const int gi = lane * 4 + i;
                xs[warp][xbuf ^ 1][gi / 3][gi % 3] = c[i];
            }
        }

        // ---- chunk projection: lane s owns timestep base+s (row s+1) ----
        if (lane < cnt) {
            const float* pr = hwarp + (lane + 1) * HSTRIDE;
            ull a0 = 0ull, c0 = 0ull, a1 = 0ull, c1 = 0ull, a2 = 0ull, c2 = 0ull;
#pragma unroll
            for (int p = 0; p < 12; p++) {
                const ulonglong2 hv = *reinterpret_cast<const ulonglong2*>(pr + 4 * p);
                FMA2(a0, hv.x, wosh[0][2 * p]); FMA2(c0, hv.y, wosh[0][2 * p + 1]);
                FMA2(a1, hv.x, wosh[1][2 * p]); FMA2(c1, hv.y, wosh[1][2 * p + 1]);
                FMA2(a2, hv.x, wosh[2][2 * p]); FMA2(c2, hv.y, wosh[2][2 * p + 1]);
            }
            const ull hl = *reinterpret_cast<const ull*>(pr + 48);
            FMA2(a0, hl, wosh[0][24]);
            FMA2(a1, hl, wosh[1][24]);
            FMA2(a2, hl, wosh[2][24]);

            ull s0, s1, s2;
            ADD2(s0, a0, c0); ADD2(s1, a1, c1); ADD2(s2, a2, c2);
            float p0l, p0h, p1l, p1h, p2l, p2h;
            unpackf2(s0, p0l, p0h);
            unpackf2(s1, p1l, p1h);
            unpackf2(s2, p2l, p2h);
            float* yo = yb + (size_t)(base + lane) * 3;
            yo[0] = p0l + p0h + bosh[0];
            yo[1] = p1l + p1h + bosh[1];
            yo[2] = p2l + p2h + bosh[2];
        }

        xbuf ^= 1;
    }
}

extern "C" void kernel_launch(void* const* d_in, const int* in_sizes, int n_in,
                              void* d_out, int out_size) {
    const float* x     = (const float*)d_in[0];
    const float* W_ih  = (const float*)d_in[1];
    const float* W_hh  = (const float*)d_in[2];
    const float* b_ih  = (const float*)d_in[3];
    const float* b_hh  = (const float*)d_in[4];
    const float* W_out = (const float*)d_in[5];
    const float* b_out = (const float*)d_in[6];
    float* y = (float*)d_out;

    rnn_kernel<<<BB / 4, 128>>>(x, W_ih, W_hh, b_ih, b_hh, W_out, b_out, y);
}

// round 6
// speedup vs baseline: 2.4162x; 2.4162x over previous
#include <cuda_runtime.h>
#include <cstdint>

#define BB 512
#define TT 2000
#define HH 50
#define CH 32
#define HSTRIDE 68     // floats per hist row, 16B-aligned rows

typedef unsigned long long ull;

__device__ __forceinline__ ull packf2(float a, float b) {
    ull r;
    asm("mov.b64 %0, {%1, %2};" : "=l"(r) : "f"(a), "f"(b));
    return r;
}
__device__ __forceinline__ void unpackf2(ull v, float& lo, float& hi) {
    asm("mov.b64 {%0, %1}, %2;" : "=f"(lo), "=f"(hi) : "l"(v));
}
#define FMA2(acc, a, b) \
    asm("fma.rn.f32x2 %0, %1, %2, %0;" : "+l"(acc) : "l"(a), "l"(b))
#define ADD2(dst, a, b) \
    asm("add.rn.f32x2 %0, %1, %2;" : "=l"(dst) : "l"(a), "l"(b))
#define CP_ASYNC16(dst_u32, src) \
    asm volatile("cp.async.ca.shared.global [%0], [%1], 16;" :: "r"(dst_u32), "l"(src))
#define CP_COMMIT() asm volatile("cp.async.commit_group;")
#define CP_WAIT0()  asm volatile("cp.async.wait_group 0;")

__global__ __launch_bounds__(128, 1)
void rnn_kernel(const float* __restrict__ x,
                const float* __restrict__ W_ih,
                const float* __restrict__ W_hh,
                const float* __restrict__ b_ih,
                const float* __restrict__ b_hh,
                const float* __restrict__ W_out,
                const float* __restrict__ b_out,
                float* __restrict__ y)
{
    // per-warp 33-row history: step s reads row s, writes row s+1; NO syncs.
    __shared__ __align__(16) float hist[4][CH + 1][HSTRIDE];   // 35,904 B
    __shared__ __align__(16) float xs[4][2][3 * CH];           //  3,072 B
    __shared__ ull  wosh[3][25];
    __shared__ float bosh[3];

    const int tid  = threadIdx.x;
    const int warp = tid >> 5;
    const int lane = tid & 31;
    const int b = blockIdx.x * 4 + warp;

    if (tid < 75) {
        const int d = tid / 25, q = tid % 25;
        wosh[d][q] = packf2(W_out[d * HH + 2 * q], W_out[d * HH + 2 * q + 1]);
    }
    if (tid < 3) bosh[tid] = b_out[tid];

    const int j0 = lane;            // < 50 always
    const int j1 = lane + 32;       // real only for lanes 0..17
    const bool j1v = (j1 < HH);

    // per-lane packed W_hh rows (25 k-pairs each); zero rows for padded j1
    ull w0[25], w1[25];
#pragma unroll
    for (int q = 0; q < 25; q++) {
        w0[q] = packf2(W_hh[j0 * HH + 2 * q], W_hh[j0 * HH + 2 * q + 1]);
        w1[q] = j1v ? packf2(W_hh[j1 * HH + 2 * q], W_hh[j1 * HH + 2 * q + 1]) : 0ull;
    }
    const float wi0a = W_ih[j0 * 3 + 0], wi0b = W_ih[j0 * 3 + 1], wi0c = W_ih[j0 * 3 + 2];
    const float bias0 = b_ih[j0] + b_hh[j0];
    const float wi1a = j1v ? W_ih[j1 * 3 + 0] : 0.f;
    const float wi1b = j1v ? W_ih[j1 * 3 + 1] : 0.f;
    const float wi1c = j1v ? W_ih[j1 * 3 + 2] : 0.f;
    const float bias1 = j1v ? (b_ih[j1] + b_hh[j1]) : 0.f;

    float* const hwarp = &hist[warp][0][0];
    hwarp[lane] = 0.f;           // h_{-1} = 0 (cols 50..63 rewritten as 0 each step)
    hwarp[lane + 32] = 0.f;

    const float* __restrict__ xb = x + (size_t)b * TT * 3;
    float* __restrict__ yb = y + (size_t)b * TT * 3;

    // stage x chunk 0 via cp.async (96 floats = lanes 0..23 x 16B)
    const uint32_t xs_base0 = (uint32_t)__cvta_generic_to_shared(&xs[warp][0][0]);
    const uint32_t xs_base1 = (uint32_t)__cvta_generic_to_shared(&xs[warp][1][0]);
    if (lane < 24) CP_ASYNC16(xs_base0 + lane * 16, xb + lane * 4);
    CP_COMMIT();
    CP_WAIT0();
    __syncthreads();     // wosh/bosh + x chunk 0 visibility (outside hot loop)

    int buf = 0;
    for (int base = 0; base < TT; base += CH) {
        const int cnt = min(CH, TT - base);     // 32 or 16, both %4 == 0

        // prefetch next chunk's x straight into the other smem buffer
        {
            const int ncnt = min(CH, TT - base - CH);
            if (base + CH < TT && lane * 16 < ncnt * 12) {
                const uint32_t dst = (buf ? xs_base0 : xs_base1) + lane * 16;
                CP_ASYNC16(dst, xb + (size_t)(base + CH) * 3 + lane * 4);
            }
            CP_COMMIT();
        }

        const float* __restrict__ xp = &xs[warp][buf][0];

        // ---- recurrence: warp-private smem, no syncs ----
        for (int g = 0; g < cnt; g += 4) {
#pragma unroll
            for (int u = 0; u < 4; u++) {
                const int s = g + u;
                const float x0 = xp[3 * s + 0];
                const float x1 = xp[3 * s + 1];
                const float x2 = xp[3 * s + 2];
                const float xh0 = fmaf(x2, wi0c, fmaf(x1, wi0b, fmaf(x0, wi0a, bias0)));
                const float xh1 = fmaf(x2, wi1c, fmaf(x1, wi1b, fmaf(x0, wi1a, bias1)));

                const float* hr = hwarp + s * HSTRIDE;
                ull a0 = packf2(xh0, 0.f), a1 = 0ull;
                ull b0 = packf2(xh1, 0.f), b1 = 0ull;
#pragma unroll
                for (int p = 0; p < 12; p++) {
                    const ulonglong2 hv = *reinterpret_cast<const ulonglong2*>(hr + 4 * p);
                    FMA2(a0, hv.x, w0[2 * p]);
                    FMA2(b0, hv.x, w1[2 * p]);
                    FMA2(a1, hv.y, w0[2 * p + 1]);
                    FMA2(b1, hv.y, w1[2 * p + 1]);
                }
                const ull hl = *reinterpret_cast<const ull*>(hr + 48);  // h[48..49]
                FMA2(a0, hl, w0[24]);
                FMA2(b0, hl, w1[24]);

                ull s0, s1;
                ADD2(s0, a0, a1);
                ADD2(s1, b0, b1);
                float l0, u0, l1, u1;
                unpackf2(s0, l0, u0);
                unpackf2(s1, l1, u1);
                const float h0 = fmaxf(l0 + u0, 0.f);
                const float h1 = fmaxf(l1 + u1, 0.f);   // exactly 0 for padded j1

                float* hw = hwarp + (s + 1) * HSTRIDE;
                hw[lane] = h0;
                hw[lane + 32] = h1;
            }
        }

        // carry h_{last} into row 0 for next chunk (same-warp in-order smem)
        hwarp[lane] = hwarp[cnt * HSTRIDE + lane];
        hwarp[lane + 32] = hwarp[cnt * HSTRIDE + lane + 32];

        // ---- chunk projection: lane s owns timestep base+s (row s+1) ----
        if (lane < cnt) {
            const float* pr = hwarp + (lane + 1) * HSTRIDE;
            ull a0 = 0ull, c0 = 0ull, a1 = 0ull, c1 = 0ull, a2 = 0ull, c2 = 0ull;
#pragma unroll
            for (int p = 0; p < 12; p++) {
                const ulonglong2 hv = *reinterpret_cast<const ulonglong2*>(pr + 4 * p);
                FMA2(a0, hv.x, wosh[0][2 * p]); FMA2(c0, hv.y, wosh[0][2 * p + 1]);
                FMA2(a1, hv.x, wosh[1][2 * p]); FMA2(c1, hv.y, wosh[1][2 * p + 1]);
                FMA2(a2, hv.x, wosh[2][2 * p]); FMA2(c2, hv.y, wosh[2][2 * p + 1]);
            }
            const ull hl = *reinterpret_cast<const ull*>(pr + 48);
            FMA2(a0, hl, wosh[0][24]);
            FMA2(a1, hl, wosh[1][24]);
            FMA2(a2, hl, wosh[2][24]);

            ull s0, s1, s2;
            ADD2(s0, a0, c0); ADD2(s1, a1, c1); ADD2(s2, a2, c2);
            float p0l, p0h, p1l, p1h, p2l, p2h;
            unpackf2(s0, p0l, p0h);
            unpackf2(s1, p1l, p1h);
            unpackf2(s2, p2l, p2h);
            float* yo = yb + (size_t)(base + lane) * 3;
            yo[0] = p0l + p0h + bosh[0];
            yo[1] = p1l + p1h + bosh[1];
            yo[2] = p2l + p2h + bosh[2];
        }

        // next chunk's x must be in smem and warp-visible
        CP_WAIT0();
        __syncwarp();
        buf ^= 1;
    }
}

extern "C" void kernel_launch(void* const* d_in, const int* in_sizes, int n_in,
                              void* d_out, int out_size) {
    const float* x     = (const float*)d_in[0];
    const float* W_ih  = (const float*)d_in[1];
    const float* W_hh  = (const float*)d_in[2];
    const float* b_ih  = (const float*)d_in[3];
    const float* b_hh  = (const float*)d_in[4];
    const float* W_out = (const float*)d_in[5];
    const float* b_out = (const float*)d_in[6];
    float* y = (float*)d_out;

    rnn_kernel<<<BB / 4, 128>>>(x, W_ih, W_hh, b_ih, b_hh, W_out, b_out, y);
}